// round 2
// baseline (speedup 1.0000x reference)
#include <cuda_runtime.h>
#include <cuda_bf16.h>
#include <cstdint>

#define MAX_N 50000
#define MAX_E 800000
#define D 128

// ------------------------- scratch (device globals) -------------------------
__device__ float g_agg1[(size_t)MAX_N * D];   // normalized neighbor means (layer 1)
__device__ int   g_cnt[MAX_N];                // in-degree
__device__ float g_inv[MAX_N];                // 1/max(deg,1)
__device__ int   g_offs[MAX_N + 1];           // CSR row offsets (by dst)
__device__ int   g_cursor[MAX_N];             // build cursors
__device__ int   g_csr[MAX_E];                // src ids grouped by dst
__device__ float g_zs[(size_t)MAX_N * 4];     // per node: z0,z1 (h@W2l^T), s0,s1 (h@W2r^T+b2)
__device__ int   g_is64;

// ------------------------- helpers ------------------------------------------
__device__ __forceinline__ long long load_idx(const void* ei, long long i) {
    if (g_is64) return ((const long long*)ei)[i];
    return (long long)((const int*)ei)[i];
}

// int64 vs int32 detection: indices < 50000 => all high words zero if int64.
__global__ void detect_kernel(const void* ei) {
    const unsigned* u = (const unsigned*)ei;
    int ok = 1;
    for (int i = 0; i < 64; i++)
        if (u[2 * i + 1] != 0u) { ok = 0; break; }
    g_is64 = ok;
}

__global__ void zero_cnt_kernel(int n) {
    int i = blockIdx.x * blockDim.x + threadIdx.x;
    if (i < n) g_cnt[i] = 0;
}

// ---------------- histogram of dst ------------------------------------------
__global__ void hist_kernel(const void* __restrict__ ei, long long E) {
    long long e = (long long)blockIdx.x * blockDim.x + threadIdx.x;
    if (e >= E) return;
    int d = (int)load_idx(ei, E + e);
    atomicAdd(&g_cnt[d], 1);
}

// ---------------- single-block exclusive scan (1024 threads) ----------------
__global__ __launch_bounds__(1024)
void scan_kernel(int n) {
    __shared__ int warp_sums[32];
    int t = threadIdx.x;
    int lane = t & 31;
    int wid = t >> 5;
    int chunk = (n + 1023) >> 10;
    int beg = t * chunk;
    int end = min(beg + chunk, n);

    int local = 0;
    for (int i = beg; i < end; i++) local += g_cnt[i];

    // inclusive scan over 1024 thread partials
    int v = local;
    #pragma unroll
    for (int o = 1; o < 32; o <<= 1) {
        int u = __shfl_up_sync(0xffffffffu, v, o);
        if (lane >= o) v += u;
    }
    if (lane == 31) warp_sums[wid] = v;
    __syncthreads();
    if (wid == 0) {
        int w = warp_sums[lane];
        #pragma unroll
        for (int o = 1; o < 32; o <<= 1) {
            int u = __shfl_up_sync(0xffffffffu, w, o);
            if (lane >= o) w += u;
        }
        warp_sums[lane] = w;
    }
    __syncthreads();
    int base = (wid > 0) ? warp_sums[wid - 1] : 0;
    int run = base + v - local;   // exclusive prefix at this thread's chunk start

    for (int i = beg; i < end; i++) {
        int c = g_cnt[i];
        g_offs[i] = run;
        g_cursor[i] = run;
        g_inv[i] = 1.0f / (float)max(c, 1);
        run += c;
    }
    if (end == n && beg < n) g_offs[n] = run;
    if (n <= beg && t == 0) g_offs[n] = 0;   // degenerate safety
}

// ---------------- CSR build --------------------------------------------------
__global__ void build_kernel(const void* __restrict__ ei, long long E) {
    long long e = (long long)blockIdx.x * blockDim.x + threadIdx.x;
    if (e >= E) return;
    int s = (int)load_idx(ei, e);
    int d = (int)load_idx(ei, E + e);
    int p = atomicAdd(&g_cursor[d], 1);
    g_csr[p] = s;
}

// ---------------- layer-1 gather aggregation: warp per node ------------------
__global__ __launch_bounds__(256)
void agg1_gather(const float* __restrict__ x, int M) {
    int node = (int)(((long long)blockIdx.x * blockDim.x + threadIdx.x) >> 5);
    int lane = threadIdx.x & 31;
    if (node >= M) return;
    int beg = g_offs[node];
    int end = g_offs[node + 1];
    float4 a0 = make_float4(0.f, 0.f, 0.f, 0.f);
    float4 a1 = make_float4(0.f, 0.f, 0.f, 0.f);
    int k = beg;
    for (; k + 1 < end; k += 2) {
        int s0 = g_csr[k];
        int s1 = g_csr[k + 1];
        float4 v0 = *(const float4*)(x + (size_t)s0 * D + lane * 4);
        float4 v1 = *(const float4*)(x + (size_t)s1 * D + lane * 4);
        a0.x += v0.x; a0.y += v0.y; a0.z += v0.z; a0.w += v0.w;
        a1.x += v1.x; a1.y += v1.y; a1.z += v1.z; a1.w += v1.w;
    }
    if (k < end) {
        int s0 = g_csr[k];
        float4 v0 = *(const float4*)(x + (size_t)s0 * D + lane * 4);
        a0.x += v0.x; a0.y += v0.y; a0.z += v0.z; a0.w += v0.w;
    }
    float inv = g_inv[node];
    float4 r;
    r.x = (a0.x + a1.x) * inv;
    r.y = (a0.y + a1.y) * inv;
    r.z = (a0.z + a1.z) * inv;
    r.w = (a0.w + a1.w) * inv;
    *(float4*)(g_agg1 + (size_t)node * D + lane * 4) = r;
}

// ---------------- fused GEMM + layer-2 projection ----------------------------
// h = relu([agg1, x] @ [W1l;W1r]^T + b1), then per row:
//   z = h @ W2l^T, s = h @ W2r^T + b2   -> g_zs (h itself never stored)
#define BM 128
#define BN 128
#define BK 16
#define TM 8
#define TN 8
__global__ __launch_bounds__(256, 2)
void gemm1_kernel(const float* __restrict__ x,
                  const float* __restrict__ W1l, const float* __restrict__ W1r,
                  const float* __restrict__ b1,
                  const float* __restrict__ W2l, const float* __restrict__ W2r,
                  const float* __restrict__ b2, int M) {
    __shared__ float As[BK][BM];
    __shared__ float Bs[BK][BN];
    int block_row = blockIdx.x * BM;
    int tid = threadIdx.x;
    int tx = tid & 15;
    int ty = tid >> 4;
    float acc[TM][TN];
    #pragma unroll
    for (int i = 0; i < TM; i++)
        #pragma unroll
        for (int j = 0; j < TN; j++) acc[i][j] = 0.f;

    #pragma unroll 1
    for (int kt = 0; kt < 2 * D; kt += BK) {
        bool isAgg = (kt < D);
        int kk0 = isAgg ? kt : kt - D;
        const float* Aptr = isAgg ? g_agg1 : x;
        const float* Wptr = isAgg ? W1l : W1r;

        #pragma unroll
        for (int p = 0; p < 2; p++) {
            int f = tid + p * 256;
            int r = f >> 2;
            int c4 = (f & 3) * 4;
            int grow = block_row + r;
            float4 v = make_float4(0.f, 0.f, 0.f, 0.f);
            if (grow < M)
                v = *(const float4*)(Aptr + (size_t)grow * D + kk0 + c4);
            As[c4 + 0][r] = v.x; As[c4 + 1][r] = v.y;
            As[c4 + 2][r] = v.z; As[c4 + 3][r] = v.w;
        }
        #pragma unroll
        for (int p = 0; p < 2; p++) {
            int f = tid + p * 256;
            int j = f >> 2;
            int c4 = (f & 3) * 4;
            float4 v = *(const float4*)(Wptr + (size_t)j * D + kk0 + c4);
            Bs[c4 + 0][j] = v.x; Bs[c4 + 1][j] = v.y;
            Bs[c4 + 2][j] = v.z; Bs[c4 + 3][j] = v.w;
        }
        __syncthreads();

        #pragma unroll
        for (int k = 0; k < BK; k++) {
            float4 a0 = *(const float4*)&As[k][ty * TM + 0];
            float4 a1 = *(const float4*)&As[k][ty * TM + 4];
            float4 b0 = *(const float4*)&Bs[k][tx * TN + 0];
            float4 b1v = *(const float4*)&Bs[k][tx * TN + 4];
            float a[TM] = {a0.x, a0.y, a0.z, a0.w, a1.x, a1.y, a1.z, a1.w};
            float b[TN] = {b0.x, b0.y, b0.z, b0.w, b1v.x, b1v.y, b1v.z, b1v.w};
            #pragma unroll
            for (int i = 0; i < TM; i++)
                #pragma unroll
                for (int j = 0; j < TN; j++)
                    acc[i][j] += a[i] * b[j];
        }
        __syncthreads();
    }

    // ---- epilogue: bias + relu in registers, then project to z/s ----
    // W2 slices for this thread's 8 columns
    int col0 = tx * TN;
    float wl0[TN], wl1[TN], wr0[TN], wr1[TN];
    #pragma unroll
    for (int j = 0; j < TN; j += 4) {
        float4 a = *(const float4*)(W2l + col0 + j);
        wl0[j] = a.x; wl0[j+1] = a.y; wl0[j+2] = a.z; wl0[j+3] = a.w;
        float4 b = *(const float4*)(W2l + D + col0 + j);
        wl1[j] = b.x; wl1[j+1] = b.y; wl1[j+2] = b.z; wl1[j+3] = b.w;
        float4 c = *(const float4*)(W2r + col0 + j);
        wr0[j] = c.x; wr0[j+1] = c.y; wr0[j+2] = c.z; wr0[j+3] = c.w;
        float4 d = *(const float4*)(W2r + D + col0 + j);
        wr1[j] = d.x; wr1[j+1] = d.y; wr1[j+2] = d.z; wr1[j+3] = d.w;
    }
    float bb2x = b2[0], bb2y = b2[1];

    #pragma unroll
    for (int i = 0; i < TM; i++) {
        float z0 = 0.f, z1 = 0.f, s0 = 0.f, s1 = 0.f;
        #pragma unroll
        for (int j = 0; j < TN; j++) {
            float h = fmaxf(acc[i][j] + b1[col0 + j], 0.f);
            z0 += h * wl0[j];
            z1 += h * wl1[j];
            s0 += h * wr0[j];
            s1 += h * wr1[j];
        }
        // reduce across the 16 tx-lanes sharing this row (within warp)
        #pragma unroll
        for (int o = 8; o; o >>= 1) {
            z0 += __shfl_xor_sync(0xffffffffu, z0, o);
            z1 += __shfl_xor_sync(0xffffffffu, z1, o);
            s0 += __shfl_xor_sync(0xffffffffu, s0, o);
            s1 += __shfl_xor_sync(0xffffffffu, s1, o);
        }
        int grow = block_row + ty * TM + i;
        if (tx == 0 && grow < M) {
            float4 o4;
            o4.x = z0; o4.y = z1;
            o4.z = s0 + bb2x; o4.w = s1 + bb2y;
            *(float4*)(g_zs + (size_t)grow * 4) = o4;
        }
    }
}

// ---------------- layer-2 gather + final output ------------------------------
__global__ __launch_bounds__(256)
void final_kernel(float* __restrict__ out, int M) {
    int node = blockIdx.x * blockDim.x + threadIdx.x;
    if (node >= M) return;
    int beg = g_offs[node];
    int end = g_offs[node + 1];
    float a0 = 0.f, a1 = 0.f;
    #pragma unroll 4
    for (int k = beg; k < end; k++) {
        int s = g_csr[k];
        float2 zv = *(const float2*)(g_zs + (size_t)s * 4);
        a0 += zv.x;
        a1 += zv.y;
    }
    float inv = g_inv[node];
    float2 st = *(const float2*)(g_zs + (size_t)node * 4 + 2);
    float2 o;
    o.x = a0 * inv + st.x;
    o.y = a1 * inv + st.y;
    *(float2*)(out + (size_t)node * 2) = o;
}

// ------------------------- launch -------------------------------------------
extern "C" void kernel_launch(void* const* d_in, const int* in_sizes, int n_in,
                              void* d_out, int out_size) {
    const float* x   = (const float*)d_in[0];
    const void*  ei  = d_in[1];
    const float* W1l = (const float*)d_in[2];
    const float* W1r = (const float*)d_in[3];
    const float* b1  = (const float*)d_in[4];
    const float* W2l = (const float*)d_in[5];
    const float* W2r = (const float*)d_in[6];
    const float* b2  = (const float*)d_in[7];
    float* out = (float*)d_out;

    int M = in_sizes[0] / D;
    long long E = in_sizes[1] / 2;

    detect_kernel<<<1, 1>>>(ei);                                   // launch 0
    zero_cnt_kernel<<<(M + 255) / 256, 256>>>(M);                  // launch 1
    hist_kernel<<<(int)((E + 255) / 256), 256>>>(ei, E);           // launch 2
    scan_kernel<<<1, 1024>>>(M);                                   // launch 3
    build_kernel<<<(int)((E + 255) / 256), 256>>>(ei, E);          // launch 4
    {
        long long threads = (long long)M * 32;                     // launch 5 (ncu target)
        agg1_gather<<<(int)((threads + 255) / 256), 256>>>(x, M);
    }
    gemm1_kernel<<<(M + BM - 1) / BM, 256>>>(x, W1l, W1r, b1,      // launch 6
                                             W2l, W2r, b2, M);
    final_kernel<<<(M + 255) / 256, 256>>>(out, M);                // launch 7
}

// round 4
// speedup vs baseline: 1.5883x; 1.5883x over previous
#include <cuda_runtime.h>
#include <cuda_bf16.h>
#include <cstdint>

#define MAX_N 50000
#define MAX_E 800000
#define D 128
#define SCAN_B 256
#define MAX_NB ((MAX_N + SCAN_B - 1) / SCAN_B)   // 196

// ------------------------- scratch (device globals) -------------------------
__device__ float g_agg1[(size_t)MAX_N * D];   // normalized neighbor means (layer 1)
__device__ int   g_cnt[MAX_N];                // in-degree
__device__ float g_inv[MAX_N];                // 1/max(deg,1)
__device__ int   g_offs[MAX_N + 1];           // CSR row offsets (by dst)
__device__ int   g_cursor[MAX_N];             // build cursors
__device__ int   g_csr[MAX_E];                // src ids grouped by dst
__device__ float g_zs[(size_t)MAX_N * 4];     // per node: z0,z1 (h@W2l^T), s0,s1 (h@W2r^T+b2)
__device__ int   g_blocksum[MAX_NB];          // scan phase 1 partials
__device__ int   g_blockbase[MAX_NB];         // scan phase 2 exclusive bases
__device__ int   g_is64;

// ------------------------- helpers ------------------------------------------
__device__ __forceinline__ long long load_idx(const void* ei, long long i) {
    if (g_is64) return ((const long long*)ei)[i];
    return (long long)((const int*)ei)[i];
}

// int64 vs int32 detection: indices < 50000 => all high words zero if int64.
__global__ void detect_kernel(const void* ei) {
    const unsigned* u = (const unsigned*)ei;
    int ok = 1;
    for (int i = 0; i < 64; i++)
        if (u[2 * i + 1] != 0u) { ok = 0; break; }
    g_is64 = ok;
}

__global__ void zero_cnt_kernel(int n) {
    int i = blockIdx.x * blockDim.x + threadIdx.x;
    if (i < n) g_cnt[i] = 0;
}

// ---------------- histogram of dst ------------------------------------------
__global__ void hist_kernel(const void* __restrict__ ei, long long E) {
    long long e = (long long)blockIdx.x * blockDim.x + threadIdx.x;
    if (e >= E) return;
    int d = (int)load_idx(ei, E + e);
    atomicAdd(&g_cnt[d], 1);
}

// ---------------- 3-phase device-wide exclusive scan -------------------------
// Phase 1: per-block sums of g_cnt
__global__ __launch_bounds__(SCAN_B)
void scan_p1(int n) {
    __shared__ int wsum[SCAN_B / 32];
    int i = blockIdx.x * SCAN_B + threadIdx.x;
    int lane = threadIdx.x & 31;
    int wid = threadIdx.x >> 5;
    int v = (i < n) ? g_cnt[i] : 0;
    #pragma unroll
    for (int o = 16; o; o >>= 1) v += __shfl_xor_sync(0xffffffffu, v, o);
    if (lane == 0) wsum[wid] = v;
    __syncthreads();
    if (threadIdx.x == 0) {
        int s = 0;
        #pragma unroll
        for (int w = 0; w < SCAN_B / 32; w++) s += wsum[w];
        g_blocksum[blockIdx.x] = s;
    }
}

// Phase 2: exclusive scan over block sums (nb <= 256), single small block.
// NOTE: second-level scan executed by ALL 32 lanes of warp 0 (full mask),
// lanes >= SCAN_B/32 carry 0 — avoids shuffle-mask divergence deadlock.
__global__ __launch_bounds__(SCAN_B)
void scan_p2(int nb) {
    __shared__ int wsum[SCAN_B / 32];
    int t = threadIdx.x;
    int lane = t & 31;
    int wid = t >> 5;
    int v = (t < nb) ? g_blocksum[t] : 0;
    int inc = v;
    #pragma unroll
    for (int o = 1; o < 32; o <<= 1) {
        int u = __shfl_up_sync(0xffffffffu, inc, o);
        if (lane >= o) inc += u;
    }
    if (lane == 31) wsum[wid] = inc;
    __syncthreads();
    if (wid == 0) {
        int w = (lane < SCAN_B / 32) ? wsum[lane] : 0;
        int winc = w;
        #pragma unroll
        for (int o = 1; o < 32; o <<= 1) {
            int u = __shfl_up_sync(0xffffffffu, winc, o);
            if (lane >= o) winc += u;
        }
        if (lane < SCAN_B / 32) wsum[lane] = winc;
    }
    __syncthreads();
    int base = (wid > 0) ? wsum[wid - 1] : 0;
    if (t < nb) g_blockbase[t] = base + inc - v;   // exclusive
}

// Phase 3: per-block exclusive scan -> offs/cursor/inv
__global__ __launch_bounds__(SCAN_B)
void scan_p3(int n) {
    __shared__ int wsum[SCAN_B / 32];
    int i = blockIdx.x * SCAN_B + threadIdx.x;
    int lane = threadIdx.x & 31;
    int wid = threadIdx.x >> 5;
    int c = (i < n) ? g_cnt[i] : 0;
    int inc = c;
    #pragma unroll
    for (int o = 1; o < 32; o <<= 1) {
        int u = __shfl_up_sync(0xffffffffu, inc, o);
        if (lane >= o) inc += u;
    }
    if (lane == 31) wsum[wid] = inc;
    __syncthreads();
    if (wid == 0) {
        int w = (lane < SCAN_B / 32) ? wsum[lane] : 0;
        int winc = w;
        #pragma unroll
        for (int o = 1; o < 32; o <<= 1) {
            int u = __shfl_up_sync(0xffffffffu, winc, o);
            if (lane >= o) winc += u;
        }
        if (lane < SCAN_B / 32) wsum[lane] = winc;
    }
    __syncthreads();
    int wbase = (wid > 0) ? wsum[wid - 1] : 0;
    int off = g_blockbase[blockIdx.x] + wbase + inc - c;   // exclusive prefix
    if (i < n) {
        g_offs[i] = off;
        g_cursor[i] = off;
        g_inv[i] = 1.0f / (float)max(c, 1);
        if (i == n - 1) g_offs[n] = off + c;
    }
}

// ---------------- CSR build --------------------------------------------------
__global__ void build_kernel(const void* __restrict__ ei, long long E) {
    long long e = (long long)blockIdx.x * blockDim.x + threadIdx.x;
    if (e >= E) return;
    int s = (int)load_idx(ei, e);
    int d = (int)load_idx(ei, E + e);
    int p = atomicAdd(&g_cursor[d], 1);
    g_csr[p] = s;
}

// ---------------- layer-1 gather aggregation: warp per node ------------------
__global__ __launch_bounds__(256)
void agg1_gather(const float* __restrict__ x, int M) {
    int node = (int)(((long long)blockIdx.x * blockDim.x + threadIdx.x) >> 5);
    int lane = threadIdx.x & 31;
    if (node >= M) return;
    int beg = g_offs[node];
    int end = g_offs[node + 1];
    float4 a0 = make_float4(0.f, 0.f, 0.f, 0.f);
    float4 a1 = make_float4(0.f, 0.f, 0.f, 0.f);
    int k = beg;
    for (; k + 1 < end; k += 2) {
        int s0 = g_csr[k];
        int s1 = g_csr[k + 1];
        float4 v0 = *(const float4*)(x + (size_t)s0 * D + lane * 4);
        float4 v1 = *(const float4*)(x + (size_t)s1 * D + lane * 4);
        a0.x += v0.x; a0.y += v0.y; a0.z += v0.z; a0.w += v0.w;
        a1.x += v1.x; a1.y += v1.y; a1.z += v1.z; a1.w += v1.w;
    }
    if (k < end) {
        int s0 = g_csr[k];
        float4 v0 = *(const float4*)(x + (size_t)s0 * D + lane * 4);
        a0.x += v0.x; a0.y += v0.y; a0.z += v0.z; a0.w += v0.w;
    }
    float inv = g_inv[node];
    float4 r;
    r.x = (a0.x + a1.x) * inv;
    r.y = (a0.y + a1.y) * inv;
    r.z = (a0.z + a1.z) * inv;
    r.w = (a0.w + a1.w) * inv;
    *(float4*)(g_agg1 + (size_t)node * D + lane * 4) = r;
}

// ---------------- fused GEMM + layer-2 projection ----------------------------
// h = relu([agg1, x] @ [W1l;W1r]^T + b1), then per row:
//   z = h @ W2l^T, s = h @ W2r^T + b2   -> g_zs (h itself never stored)
#define BM 128
#define BN 128
#define BK 16
#define TM 8
#define TN 8
__global__ __launch_bounds__(256, 2)
void gemm1_kernel(const float* __restrict__ x,
                  const float* __restrict__ W1l, const float* __restrict__ W1r,
                  const float* __restrict__ b1,
                  const float* __restrict__ W2l, const float* __restrict__ W2r,
                  const float* __restrict__ b2, int M) {
    __shared__ float As[BK][BM];
    __shared__ float Bs[BK][BN];
    int block_row = blockIdx.x * BM;
    int tid = threadIdx.x;
    int tx = tid & 15;
    int ty = tid >> 4;
    float acc[TM][TN];
    #pragma unroll
    for (int i = 0; i < TM; i++)
        #pragma unroll
        for (int j = 0; j < TN; j++) acc[i][j] = 0.f;

    #pragma unroll 1
    for (int kt = 0; kt < 2 * D; kt += BK) {
        bool isAgg = (kt < D);
        int kk0 = isAgg ? kt : kt - D;
        const float* Aptr = isAgg ? g_agg1 : x;
        const float* Wptr = isAgg ? W1l : W1r;

        #pragma unroll
        for (int p = 0; p < 2; p++) {
            int f = tid + p * 256;
            int r = f >> 2;
            int c4 = (f & 3) * 4;
            int grow = block_row + r;
            float4 v = make_float4(0.f, 0.f, 0.f, 0.f);
            if (grow < M)
                v = *(const float4*)(Aptr + (size_t)grow * D + kk0 + c4);
            As[c4 + 0][r] = v.x; As[c4 + 1][r] = v.y;
            As[c4 + 2][r] = v.z; As[c4 + 3][r] = v.w;
        }
        #pragma unroll
        for (int p = 0; p < 2; p++) {
            int f = tid + p * 256;
            int j = f >> 2;
            int c4 = (f & 3) * 4;
            float4 v = *(const float4*)(Wptr + (size_t)j * D + kk0 + c4);
            Bs[c4 + 0][j] = v.x; Bs[c4 + 1][j] = v.y;
            Bs[c4 + 2][j] = v.z; Bs[c4 + 3][j] = v.w;
        }
        __syncthreads();

        #pragma unroll
        for (int k = 0; k < BK; k++) {
            float4 a0 = *(const float4*)&As[k][ty * TM + 0];
            float4 a1 = *(const float4*)&As[k][ty * TM + 4];
            float4 b0 = *(const float4*)&Bs[k][tx * TN + 0];
            float4 b1v = *(const float4*)&Bs[k][tx * TN + 4];
            float a[TM] = {a0.x, a0.y, a0.z, a0.w, a1.x, a1.y, a1.z, a1.w};
            float b[TN] = {b0.x, b0.y, b0.z, b0.w, b1v.x, b1v.y, b1v.z, b1v.w};
            #pragma unroll
            for (int i = 0; i < TM; i++)
                #pragma unroll
                for (int j = 0; j < TN; j++)
                    acc[i][j] += a[i] * b[j];
        }
        __syncthreads();
    }

    // ---- epilogue: bias + relu in registers, then project to z/s ----
    int col0 = tx * TN;
    float wl0[TN], wl1[TN], wr0[TN], wr1[TN];
    #pragma unroll
    for (int j = 0; j < TN; j += 4) {
        float4 a = *(const float4*)(W2l + col0 + j);
        wl0[j] = a.x; wl0[j+1] = a.y; wl0[j+2] = a.z; wl0[j+3] = a.w;
        float4 b = *(const float4*)(W2l + D + col0 + j);
        wl1[j] = b.x; wl1[j+1] = b.y; wl1[j+2] = b.z; wl1[j+3] = b.w;
        float4 c = *(const float4*)(W2r + col0 + j);
        wr0[j] = c.x; wr0[j+1] = c.y; wr0[j+2] = c.z; wr0[j+3] = c.w;
        float4 d = *(const float4*)(W2r + D + col0 + j);
        wr1[j] = d.x; wr1[j+1] = d.y; wr1[j+2] = d.z; wr1[j+3] = d.w;
    }
    float bb2x = b2[0], bb2y = b2[1];

    #pragma unroll
    for (int i = 0; i < TM; i++) {
        float z0 = 0.f, z1 = 0.f, s0 = 0.f, s1 = 0.f;
        #pragma unroll
        for (int j = 0; j < TN; j++) {
            float h = fmaxf(acc[i][j] + b1[col0 + j], 0.f);
            z0 += h * wl0[j];
            z1 += h * wl1[j];
            s0 += h * wr0[j];
            s1 += h * wr1[j];
        }
        #pragma unroll
        for (int o = 8; o; o >>= 1) {
            z0 += __shfl_xor_sync(0xffffffffu, z0, o);
            z1 += __shfl_xor_sync(0xffffffffu, z1, o);
            s0 += __shfl_xor_sync(0xffffffffu, s0, o);
            s1 += __shfl_xor_sync(0xffffffffu, s1, o);
        }
        int grow = block_row + ty * TM + i;
        if (tx == 0 && grow < M) {
            float4 o4;
            o4.x = z0; o4.y = z1;
            o4.z = s0 + bb2x; o4.w = s1 + bb2y;
            *(float4*)(g_zs + (size_t)grow * 4) = o4;
        }
    }
}

// ---------------- layer-2 gather + final output ------------------------------
__global__ __launch_bounds__(256)
void final_kernel(float* __restrict__ out, int M) {
    int node = blockIdx.x * blockDim.x + threadIdx.x;
    if (node >= M) return;
    int beg = g_offs[node];
    int end = g_offs[node + 1];
    float a0 = 0.f, a1 = 0.f;
    #pragma unroll 4
    for (int k = beg; k < end; k++) {
        int s = g_csr[k];
        float2 zv = *(const float2*)(g_zs + (size_t)s * 4);
        a0 += zv.x;
        a1 += zv.y;
    }
    float inv = g_inv[node];
    float2 st = *(const float2*)(g_zs + (size_t)node * 4 + 2);
    float2 o;
    o.x = a0 * inv + st.x;
    o.y = a1 * inv + st.y;
    *(float2*)(out + (size_t)node * 2) = o;
}

// ------------------------- launch -------------------------------------------
extern "C" void kernel_launch(void* const* d_in, const int* in_sizes, int n_in,
                              void* d_out, int out_size) {
    const float* x   = (const float*)d_in[0];
    const void*  ei  = d_in[1];
    const float* W1l = (const float*)d_in[2];
    const float* W1r = (const float*)d_in[3];
    const float* b1  = (const float*)d_in[4];
    const float* W2l = (const float*)d_in[5];
    const float* W2r = (const float*)d_in[6];
    const float* b2  = (const float*)d_in[7];
    float* out = (float*)d_out;

    int M = in_sizes[0] / D;
    long long E = in_sizes[1] / 2;
    int nb = (M + SCAN_B - 1) / SCAN_B;

    detect_kernel<<<1, 1>>>(ei);                                   // 0
    zero_cnt_kernel<<<(M + 255) / 256, 256>>>(M);                  // 1
    hist_kernel<<<(int)((E + 255) / 256), 256>>>(ei, E);           // 2
    scan_p1<<<nb, SCAN_B>>>(M);                                    // 3
    scan_p2<<<1, SCAN_B>>>(nb);                                    // 4
    scan_p3<<<nb, SCAN_B>>>(M);                                    // 5
    build_kernel<<<(int)((E + 255) / 256), 256>>>(ei, E);          // 6
    {
        long long threads = (long long)M * 32;
        agg1_gather<<<(int)((threads + 255) / 256), 256>>>(x, M);  // 7
    }
    gemm1_kernel<<<(M + BM - 1) / BM, 256>>>(x, W1l, W1r, b1,      // 8
                                             W2l, W2r, b2, M);
    final_kernel<<<(M + 255) / 256, 256>>>(out, M);                // 9
}